// round 16
// baseline (speedup 1.0000x reference)
#include <cuda_runtime.h>
#include <cstdint>
#include <cstddef>
#include <math.h>

#define FULLMASK 0xFFFFFFFFu

// ----------------------------- static scratch ------------------------------
__device__ __align__(16) unsigned       g_xp[8192 * 28];    // packed input rows
__device__ __align__(16) unsigned       g_a1[8192 * 400];   // L1 acts, bit c = channel
__device__ __align__(16) unsigned short g_a2[8192 * 144];   // L2 acts, bit c = channel

__device__ unsigned       g_w1p[32 * 9];     // [f][u], bits v
__device__ unsigned       g_w2p[16 * 81];    // [f][tap], bits c(32)
__device__ unsigned short g_w3p[8 * 81];     // [f][tap], bits c(16)
__device__ unsigned       g_wlp[10 * 4];     // [f][p], bit (c + 8q)
__device__ float          g_sbl[10];

__device__ int g_T[784];
__device__ int g_S1[400 * 16];   // packed: low16 = ch c, high16 = ch c+16
__device__ int g_S2[144 * 8];    // packed: low16 = ch c, high16 = ch c+8
__device__ int g_lim1[32], g_lim2[16], g_lim3[8];   // popc limits (acc <= lim)
__device__ int g_c0;

// --------------------- prep: zero counters + pack weights ------------------
__global__ __launch_bounds__(256) void prepk(
    const float* __restrict__ w1, const float* __restrict__ w2,
    const float* __restrict__ w3, const float* __restrict__ wl,
    const float* __restrict__ bl) {
    int idx = blockIdx.x * 256 + threadIdx.x;
    if (idx < 6400) g_S1[idx] = 0;
    if (idx < 1152) g_S2[idx] = 0;
    if (idx < 784)  g_T[idx]  = 0;
    if (idx == 0)   g_c0 = 0;
    if (idx < 288) {
        int f = idx / 9, u = idx % 9; unsigned m = 0;
        for (int v = 0; v < 9; v++)
            if (w1[f * 81 + u * 9 + v] >= 0.f) m |= 1u << v;
        g_w1p[idx] = m;
    } else if (idx < 1584) {
        int e = idx - 288, f = e / 81, t2 = e % 81; unsigned m = 0;
        for (int c = 0; c < 32; c++)
            if (w2[f * 2592 + c * 81 + t2] >= 0.f) m |= 1u << c;
        g_w2p[e] = m;
    } else if (idx < 2232) {
        int e = idx - 1584, f = e / 81, t3 = e % 81; unsigned m = 0;
        for (int c = 0; c < 16; c++)
            if (w3[f * 1296 + c * 81 + t3] >= 0.f) m |= 1u << c;
        g_w3p[e] = (unsigned short)m;
    } else if (idx < 2272) {
        int e = idx - 2232, f = e / 4, p = e % 4; unsigned m = 0;
        for (int q = 0; q < 4; q++)
            for (int c = 0; c < 8; c++)
                if (wl[f * 128 + c * 16 + (4 * p + q)] >= 0.f) m |= 1u << (c + 8 * q);
        g_wlp[e] = m;
    } else if (idx < 2282) {
        int f = idx - 2272;
        g_sbl[f] = (bl[f] >= 0.f) ? 1.f : -1.f;
    }
}

// ------- binarize x + batch counts; LAST BLOCK computes g_lim1 -------------
__global__ __launch_bounds__(256) void binxk(const float* __restrict__ x) {
    __shared__ unsigned mrow[8][28];
    __shared__ int Ts[784];
    __shared__ int R[28 * 9];
    __shared__ int A[81];
    __shared__ int lastf;
    int tid = threadIdx.x, lane = tid & 31, w = tid >> 5;
    int n = blockIdx.x * 8 + w;
    const float* xi = x + (size_t)n * 784;
    float va[28];
#pragma unroll
    for (int row = 0; row < 28; row++)
        va[row] = (lane < 28) ? xi[row * 28 + lane] : -1.f;
#pragma unroll
    for (int row = 0; row < 28; row++) {
        unsigned m = __ballot_sync(FULLMASK, va[row] >= 0.f);
        if (lane == 0) { g_xp[n * 28 + row] = m; mrow[w][row] = m; }
    }
    __syncthreads();
    for (int t = tid; t < 784; t += 256) {
        int row = t / 28, col = t % 28;
        int s = 0;
#pragma unroll
        for (int ww = 0; ww < 8; ww++) s += (mrow[ww][row] >> col) & 1;
        atomicAdd(&g_T[t], s);
    }

    // last-block tail: thresh1
    __threadfence();
    if (tid == 0) lastf = (atomicAdd(&g_c0, 1) == (int)gridDim.x - 1);
    __syncthreads();
    if (!lastf) return;
    __threadfence();
    for (int t = tid; t < 784; t += 256) Ts[t] = g_T[t];
    __syncthreads();
    for (int e = tid; e < 252; e += 256) {
        int r = e / 9, v = e % 9, s = 0;
#pragma unroll
        for (int j = 0; j < 20; j++) s += Ts[r * 28 + j + v];
        R[e] = s;
    }
    __syncthreads();
    for (int e = tid; e < 81; e += 256) {
        int u = e / 9, v = e % 9, s = 0;
#pragma unroll
        for (int i = 0; i < 20; i++) s += R[(i + u) * 9 + v];
        A[e] = s;
    }
    __syncthreads();
    if (tid < 32) {
        long long s = 0;
        for (int u = 0; u < 9; u++) {
            unsigned wrow = g_w1p[tid * 9 + u];
            for (int v = 0; v < 9; v++) {
                long long a = 2LL * A[u * 9 + v] - 3276800LL;
                s += ((wrow >> v) & 1u) ? a : -a;
            }
        }
        int t1 = (int)ceil((double)s / 3276800.0);
        g_lim1[tid] = (81 - t1) >> 1;     // y>=t1  <=>  popc-acc <= lim
    }
}

// ------------------------------ conv1 --------------------------------------
// Warp = image. Phase 1: pack each 81-bit window into 3 smem words.
// Phase 2: lane = filter, 3 popc per position, ballot emits packed a1 word.
// Epilogue: block counts its own 8 images' channel bits into packed g_S1.
__global__ __launch_bounds__(256) void conv1k() {
    __shared__ unsigned win[8][1200];      // [warp][p*3+k]
    __shared__ unsigned xr[8][28];
    int tid = threadIdx.x, lane = tid & 31, w = tid >> 5;
    int n = blockIdx.x * 8 + w;
    if (lane < 28) xr[w][lane] = g_xp[n * 28 + lane];
    unsigned fw0, fw1, fw2;
    {
        const unsigned* wp = &g_w1p[lane * 9];
        fw0 = wp[0] | (wp[1] << 9) | (wp[2] << 18);
        fw1 = wp[3] | (wp[4] << 9) | (wp[5] << 18);
        fw2 = wp[6] | (wp[7] << 9) | (wp[8] << 18);
    }
    int mylim = g_lim1[lane];
    __syncwarp();

    const unsigned* xrw = xr[w];
    for (int p = lane; p < 400; p += 32) {
        int i = p / 20, j = p % 20;
        unsigned s0 = (xrw[i + 0] >> j) & 0x1FFu, s1 = (xrw[i + 1] >> j) & 0x1FFu;
        unsigned s2 = (xrw[i + 2] >> j) & 0x1FFu, s3 = (xrw[i + 3] >> j) & 0x1FFu;
        unsigned s4 = (xrw[i + 4] >> j) & 0x1FFu, s5 = (xrw[i + 5] >> j) & 0x1FFu;
        unsigned s6 = (xrw[i + 6] >> j) & 0x1FFu, s7 = (xrw[i + 7] >> j) & 0x1FFu;
        unsigned s8 = (xrw[i + 8] >> j) & 0x1FFu;
        win[w][p * 3 + 0] = s0 | (s1 << 9) | (s2 << 18);
        win[w][p * 3 + 1] = s3 | (s4 << 9) | (s5 << 18);
        win[w][p * 3 + 2] = s6 | (s7 << 9) | (s8 << 18);
    }
    __syncwarp();

    unsigned* outp = &g_a1[n * 400];
    const unsigned* wb = win[w];
    for (int i = 0; i < 20; i++) {
        unsigned myw = 0;
#pragma unroll
        for (int j = 0; j < 20; j++) {
            int p3 = (i * 20 + j) * 3;
            int acc = __popc(wb[p3] ^ fw0) + __popc(wb[p3 + 1] ^ fw1)
                    + __popc(wb[p3 + 2] ^ fw2);
            unsigned b = __ballot_sync(FULLMASK, acc <= mylim);
            if (lane == j) myw = b;
        }
        if (lane < 20) outp[i * 20 + lane] = myw;
    }

    // ---- epilogue: count channel bits of this block's 8 images ----
    __syncthreads();
    const unsigned* a1b = &g_a1[(size_t)blockIdx.x * 8 * 400];
    for (int p = tid; p < 400; p += 256) {
        unsigned cnt8[8];
#pragma unroll
        for (int c = 0; c < 8; c++) cnt8[c] = 0;
#pragma unroll
        for (int im = 0; im < 8; im++) {
            unsigned wd = a1b[im * 400 + p];
#pragma unroll
            for (int c = 0; c < 8; c++) cnt8[c] += (wd >> c) & 0x01010101u;
        }
#pragma unroll
        for (int c = 0; c < 8; c++) {
            atomicAdd(&g_S1[p * 16 + c],     (int)(cnt8[c] & 0x00FF00FFu));
            atomicAdd(&g_S1[p * 16 + c + 8], (int)((cnt8[c] >> 8) & 0x00FF00FFu));
        }
    }
}

// ---------------- thresh2k: g_S1 -> g_lim2 (single block) ------------------
__global__ __launch_bounds__(256) void thresh2k() {
    extern __shared__ int tsm[];
    int* S1s = tsm;            // 12800 ints (unpacked [p][c32])
    int* R   = tsm + 12800;    // 5760
    int* WS  = tsm + 18560;    // 2592
    int tid = threadIdx.x;
    for (int e = tid; e < 6400; e += 256) {
        unsigned pk = (unsigned)g_S1[e];
        int p = e >> 4, c = e & 15;
        S1s[p * 32 + c]      = (int)(pk & 0xFFFFu);
        S1s[p * 32 + c + 16] = (int)(pk >> 16);
    }
    __syncthreads();
    for (int e = tid; e < 5760; e += 256) {
        int c = e & 31, rv = e >> 5, r = rv / 9, v = rv % 9, s = 0;
#pragma unroll
        for (int j = 0; j < 12; j++) s += S1s[(r * 20 + j + v) * 32 + c];
        R[e] = s;
    }
    __syncthreads();
    for (int e = tid; e < 2592; e += 256) {
        int c = e & 31, uv = e >> 5, u = uv / 9, v = uv % 9, s = 0;
#pragma unroll
        for (int i = 0; i < 12; i++) s += R[((i + u) * 9 + v) * 32 + c];
        WS[e] = 2 * s - 1179648;
    }
    __syncthreads();
    int lane = tid & 31, wp = tid >> 5;
    for (int ff = 0; ff < 2; ff++) {
        int f = wp * 2 + ff;
        long long s = 0;
        for (int t = lane; t < 81; t += 32) {
            unsigned wdw = g_w2p[f * 81 + t];
#pragma unroll
            for (int c = 0; c < 32; c++) {
                int term = WS[t * 32 + c];
                s += ((wdw >> c) & 1u) ? term : -term;
            }
        }
        for (int o = 16; o > 0; o >>= 1) s += __shfl_down_sync(FULLMASK, s, o);
        if (lane == 0) {
            int t2 = (int)ceil((double)s / 1179648.0);
            g_lim2[f] = (2592 - t2) >> 1;
        }
    }
}

// ------------------------------ conv2 --------------------------------------
// 2 images/block, 384 threads, 1 task/thread: task = (img, f, row-pair, j-half).
// warp w: img = w/6, row-pair = w%6; half-warp = j-half, lane&15 = filter.
// Word-holder lanes also count channel bits into packed g_S2.
__global__ __launch_bounds__(384) void conv2k() {
    __shared__ unsigned xs[2][440];
    __shared__ unsigned ws[1296];
    __shared__ int lim[16];
    int tid = threadIdx.x, lane = tid & 31;
    int n0 = blockIdx.x * 2;
    for (int t = tid; t < 800; t += 384) {
        int im = t / 400;
        xs[im][t - im * 400] = g_a1[(size_t)n0 * 400 + t];
    }
    for (int t = tid; t < 1296; t += 384) ws[t] = g_w2p[t];
    if (tid < 16) lim[tid] = g_lim2[tid];
    __syncthreads();

    int f = tid & 15;
    int jh = (tid >> 4) & 1;
    int w = tid >> 5;
    int img = w / 6, ip = w - img * 6;     // row-pair 0..5
    int i0 = ip * 2;
    const unsigned* wb = &ws[f * 81];
    const unsigned* xbase = &xs[img][i0 * 20 + jh * 6];

    unsigned rb0[14], rb1[14], rb2[14];
    int at[6], ab[6];
#pragma unroll
    for (int k = 0; k < 6; k++) { at[k] = 0; ab[k] = 0; }
#pragma unroll
    for (int v = 0; v < 14; v++) { rb0[v] = xbase[v]; rb1[v] = xbase[20 + v]; }

#define C2BODY(TP, BT, NX, U)                                            \
    {                                                                    \
        _Pragma("unroll")                                                \
        for (int v = 0; v < 14; v++) NX[v] = xbase[((U) + 2) * 20 + v];  \
        _Pragma("unroll")                                                \
        for (int v = 0; v < 9; v++) {                                    \
            unsigned wv = wb[(U) * 9 + v];                               \
            _Pragma("unroll")                                            \
            for (int jj = 0; jj < 6; jj++) {                             \
                at[jj] += __popc(TP[jj + v] ^ wv);                       \
                ab[jj] += __popc(BT[jj + v] ^ wv);                       \
            }                                                            \
        }                                                                \
    }

#pragma unroll 1
    for (int uu = 0; uu < 9; uu += 3) {
        C2BODY(rb0, rb1, rb2, uu + 0);
        C2BODY(rb1, rb2, rb0, uu + 1);
        C2BODY(rb2, rb0, rb1, uu + 2);
    }
#undef C2BODY

    int limf = lim[f];
    unsigned myword = 0;
#pragma unroll
    for (int k = 0; k < 6; k++) {
        unsigned b = __ballot_sync(FULLMASK, at[k] <= limf);
        if ((lane & 15) == k) myword = (lane < 16) ? (b & 0xFFFFu) : (b >> 16);
    }
#pragma unroll
    for (int k = 0; k < 6; k++) {
        unsigned b = __ballot_sync(FULLMASK, ab[k] <= limf);
        if ((lane & 15) == k + 6) myword = (lane < 16) ? (b & 0xFFFFu) : (b >> 16);
    }
    int kl = lane & 15;
    if (kl < 12) {
        int row = i0 + (kl >= 6);
        int col = jh * 6 + (kl % 6);
        int pix = row * 12 + col;
        g_a2[(size_t)(n0 + img) * 144 + pix] = (unsigned short)myword;
#pragma unroll
        for (int c = 0; c < 8; c++) {
            unsigned v = ((myword >> c) & 1u) | (((myword >> (c + 8)) & 1u) << 16);
            atomicAdd(&g_S2[pix * 8 + c], (int)v);
        }
    }
}

// ---------------- thresh3k: g_S2 -> g_lim3 (single block) ------------------
__global__ __launch_bounds__(256) void thresh3k() {
    __shared__ int S2s[144 * 16];
    __shared__ int WS[1296];
    int tid = threadIdx.x;
    for (int e = tid; e < 1152; e += 256) {
        unsigned pk = (unsigned)g_S2[e];
        int p = e >> 3, c = e & 7;
        S2s[p * 16 + c]     = (int)(pk & 0xFFFFu);
        S2s[p * 16 + c + 8] = (int)(pk >> 16);
    }
    __syncthreads();
    for (int e = tid; e < 1296; e += 256) {
        int c = e & 15, uv = e >> 4, u = uv / 9, v = uv % 9, s = 0;
#pragma unroll
        for (int i = 0; i < 4; i++)
#pragma unroll
            for (int j = 0; j < 4; j++)
                s += S2s[((i + u) * 12 + (j + v)) * 16 + c];
        WS[e] = 2 * s - 131072;
    }
    __syncthreads();
    int lane = tid & 31, f = tid >> 5;
    long long s = 0;
    for (int t = lane; t < 81; t += 32) {
        unsigned wdw = g_w3p[f * 81 + t];
#pragma unroll
        for (int c = 0; c < 16; c++) {
            int term = WS[(t << 4) + c];
            s += ((wdw >> c) & 1u) ? term : -term;
        }
    }
    for (int o = 16; o > 0; o >>= 1) s += __shfl_down_sync(FULLMASK, s, o);
    if (lane == 0) {
        int t3 = (int)ceil((double)s / 131072.0);
        g_lim3[f] = (1296 - t3) >> 1;
    }
}

// --------------- conv3 + binarize + linear layer, fused --------------------
__global__ __launch_bounds__(256) void conv34k(float* __restrict__ out) {
    __shared__ unsigned short xs[2][144];
    __shared__ unsigned short ws[8 * 88];   // stride 88 kills bank conflicts
    __shared__ int lim[8];
    __shared__ unsigned a3s[2][4];
    int tid = threadIdx.x;
    int n0 = blockIdx.x * 2;
    for (int t = tid; t < 288; t += 256) {
        int img = t / 144, pp = t % 144;
        xs[img][pp] = g_a2[(size_t)(n0 + img) * 144 + pp];
    }
    for (int t = tid; t < 648; t += 256) {
        int f = t / 81, k = t % 81;
        ws[f * 88 + k] = g_w3p[t];
    }
    if (tid < 8) lim[tid] = g_lim3[tid];
    __syncthreads();
    int half = tid >> 7, ht = tid & 127;
    int f = ht & 7, pix = ht >> 3, i = pix >> 2, j = pix & 3;
    const unsigned short* xb = &xs[half][i * 12 + j];
    const unsigned short* wb = &ws[f * 88];
    int acc = 0;
#pragma unroll
    for (int u = 0; u < 9; u++)
#pragma unroll
        for (int v = 0; v < 9; v++)
            acc += __popc((unsigned)(xb[u * 12 + v] ^ wb[u * 9 + v]));
    // ballot word (pix>>2) with bit ((pix&3)*8+f) — exactly g_wlp layout
    unsigned bw = __ballot_sync(FULLMASK, acc <= lim[f]);
    if ((tid & 31) == 0) a3s[half][ht >> 5] = bw;
    __syncthreads();
    if (ht < 10) {
        const unsigned* wp = &g_wlp[ht * 4];
        int pop = 0;
#pragma unroll
        for (int p4 = 0; p4 < 4; p4++) pop += __popc(a3s[half][p4] ^ wp[p4]);
        out[(n0 + half) * 10 + ht] = (float)(128 - 2 * pop) + g_sbl[ht];
    }
}

// ------------------------------ launch -------------------------------------
// Inputs identified BY ELEMENT COUNT (all 9 distinct): robust to any order.
extern "C" void kernel_launch(void* const* d_in, const int* in_sizes, int n_in,
                              void* d_out, int out_size) {
    (void)out_size;
    const float *x = 0, *w1 = 0, *w2 = 0, *w3 = 0, *wl = 0, *bl = 0;
    for (int i = 0; i < n_in; i++) {
        const float* p = (const float*)d_in[i];
        switch (in_sizes[i]) {
            case 6422528: x  = p; break;
            case 2592:    w1 = p; break;
            case 41472:   w2 = p; break;
            case 10368:   w3 = p; break;
            case 1280:    wl = p; break;
            case 10:      bl = p; break;
            default: break;   // b1/b2/b3 cancel under BN+sign
        }
    }
    cudaFuncSetAttribute(thresh2k, cudaFuncAttributeMaxDynamicSharedMemorySize, 84608);

    prepk   <<<50,   256>>>(w1, w2, w3, wl, bl);
    binxk   <<<1024, 256>>>(x);
    conv1k  <<<1024, 256>>>();
    thresh2k<<<1,    256, 84608>>>();
    conv2k  <<<4096, 384>>>();
    thresh3k<<<1,    256>>>();
    conv34k <<<4096, 256>>>((float*)d_out);
}

// round 17
// speedup vs baseline: 1.5547x; 1.5547x over previous
#include <cuda_runtime.h>
#include <cstdint>
#include <cstddef>
#include <math.h>

#define FULLMASK 0xFFFFFFFFu

// ----------------------------- static scratch ------------------------------
__device__ __align__(16) unsigned       g_xp[8192 * 28];    // packed input rows
__device__ __align__(16) unsigned       g_a1[8192 * 400];   // L1 acts, bit c = channel
__device__ __align__(16) unsigned short g_a2[8192 * 144];   // L2 acts, bit c = channel

__device__ unsigned       g_w1p[32 * 9];     // [f][u], bits v
__device__ unsigned       g_w2p[16 * 81];    // [f][tap], bits c(32)
__device__ unsigned short g_w3p[8 * 81];     // [f][tap], bits c(16)
__device__ unsigned       g_wlp[10 * 4];     // [f][p], bit (c + 8q)
__device__ float          g_sbl[10];

__device__ int g_T[784];
__device__ int g_S1[400 * 32];
__device__ int g_S2[144 * 16];
__device__ int g_lim1[32], g_lim2[16], g_lim3[8];   // popc limits (acc <= lim)
__device__ int g_c0, g_c1, g_c2;

// --------------------- prep: zero counters + pack weights ------------------
__global__ __launch_bounds__(256) void prepk(
    const float* __restrict__ w1, const float* __restrict__ w2,
    const float* __restrict__ w3, const float* __restrict__ wl,
    const float* __restrict__ bl) {
    int idx = blockIdx.x * 256 + threadIdx.x;
    if (idx < 12800) g_S1[idx] = 0;
    if (idx < 2304)  g_S2[idx] = 0;
    if (idx < 784)   g_T[idx]  = 0;
    if (idx == 0) { g_c0 = 0; g_c1 = 0; g_c2 = 0; }
    if (idx < 288) {
        int f = idx / 9, u = idx % 9; unsigned m = 0;
        for (int v = 0; v < 9; v++)
            if (w1[f * 81 + u * 9 + v] >= 0.f) m |= 1u << v;
        g_w1p[idx] = m;
    } else if (idx < 1584) {
        int e = idx - 288, f = e / 81, t2 = e % 81; unsigned m = 0;
        for (int c = 0; c < 32; c++)
            if (w2[f * 2592 + c * 81 + t2] >= 0.f) m |= 1u << c;
        g_w2p[e] = m;
    } else if (idx < 2232) {
        int e = idx - 1584, f = e / 81, t3 = e % 81; unsigned m = 0;
        for (int c = 0; c < 16; c++)
            if (w3[f * 1296 + c * 81 + t3] >= 0.f) m |= 1u << c;
        g_w3p[e] = (unsigned short)m;
    } else if (idx < 2272) {
        int e = idx - 2232, f = e / 4, p = e % 4; unsigned m = 0;
        for (int q = 0; q < 4; q++)
            for (int c = 0; c < 8; c++)
                if (wl[f * 128 + c * 16 + (4 * p + q)] >= 0.f) m |= 1u << (c + 8 * q);
        g_wlp[e] = m;
    } else if (idx < 2282) {
        int f = idx - 2272;
        g_sbl[f] = (bl[f] >= 0.f) ? 1.f : -1.f;
    }
}

// ------- binarize x + batch counts; LAST BLOCK computes g_lim1 -------------
__global__ __launch_bounds__(256) void binxk(const float* __restrict__ x) {
    __shared__ unsigned mrow[8][28];
    __shared__ int Ts[784];
    __shared__ int R[28 * 9];
    __shared__ int A[81];
    __shared__ int lastf;
    int tid = threadIdx.x, lane = tid & 31, w = tid >> 5;
    int n = blockIdx.x * 8 + w;
    const float* xi = x + (size_t)n * 784;
    float va[28];
#pragma unroll
    for (int row = 0; row < 28; row++)
        va[row] = (lane < 28) ? xi[row * 28 + lane] : -1.f;
#pragma unroll
    for (int row = 0; row < 28; row++) {
        unsigned m = __ballot_sync(FULLMASK, va[row] >= 0.f);
        if (lane == 0) { g_xp[n * 28 + row] = m; mrow[w][row] = m; }
    }
    __syncthreads();
    for (int t = tid; t < 784; t += 256) {
        int row = t / 28, col = t % 28;
        int s = 0;
#pragma unroll
        for (int ww = 0; ww < 8; ww++) s += (mrow[ww][row] >> col) & 1;
        atomicAdd(&g_T[t], s);
    }

    // last-block tail: thresh1
    __threadfence();
    if (tid == 0) lastf = (atomicAdd(&g_c0, 1) == (int)gridDim.x - 1);
    __syncthreads();
    if (!lastf) return;
    __threadfence();
    for (int t = tid; t < 784; t += 256) Ts[t] = g_T[t];
    __syncthreads();
    for (int e = tid; e < 252; e += 256) {
        int r = e / 9, v = e % 9, s = 0;
#pragma unroll
        for (int j = 0; j < 20; j++) s += Ts[r * 28 + j + v];
        R[e] = s;
    }
    __syncthreads();
    for (int e = tid; e < 81; e += 256) {
        int u = e / 9, v = e % 9, s = 0;
#pragma unroll
        for (int i = 0; i < 20; i++) s += R[(i + u) * 9 + v];
        A[e] = s;
    }
    __syncthreads();
    if (tid < 32) {
        long long s = 0;
        for (int u = 0; u < 9; u++) {
            unsigned wrow = g_w1p[tid * 9 + u];
            for (int v = 0; v < 9; v++) {
                long long a = 2LL * A[u * 9 + v] - 3276800LL;
                s += ((wrow >> v) & 1u) ? a : -a;
            }
        }
        int t1 = (int)ceil((double)s / 3276800.0);
        g_lim1[tid] = (81 - t1) >> 1;     // y>=t1  <=>  popc-acc <= lim
    }
}

// ------------------------------ conv1 --------------------------------------
// Warp = image. Phase 1: pack each 81-bit window into 3 smem words.
// Phase 2: lane = filter, 3 popc per position, ballot emits packed a1 word.
__global__ __launch_bounds__(256) void conv1k() {
    __shared__ unsigned win[8][1200];      // [warp][p*3+k]
    __shared__ unsigned xr[8][28];
    int tid = threadIdx.x, lane = tid & 31, w = tid >> 5;
    int n = blockIdx.x * 8 + w;
    if (lane < 28) xr[w][lane] = g_xp[n * 28 + lane];
    unsigned fw0, fw1, fw2;
    {
        const unsigned* wp = &g_w1p[lane * 9];
        fw0 = wp[0] | (wp[1] << 9) | (wp[2] << 18);
        fw1 = wp[3] | (wp[4] << 9) | (wp[5] << 18);
        fw2 = wp[6] | (wp[7] << 9) | (wp[8] << 18);
    }
    int mylim = g_lim1[lane];
    __syncwarp();

    const unsigned* xrw = xr[w];
    for (int p = lane; p < 400; p += 32) {
        int i = p / 20, j = p % 20;
        unsigned s0 = (xrw[i + 0] >> j) & 0x1FFu, s1 = (xrw[i + 1] >> j) & 0x1FFu;
        unsigned s2 = (xrw[i + 2] >> j) & 0x1FFu, s3 = (xrw[i + 3] >> j) & 0x1FFu;
        unsigned s4 = (xrw[i + 4] >> j) & 0x1FFu, s5 = (xrw[i + 5] >> j) & 0x1FFu;
        unsigned s6 = (xrw[i + 6] >> j) & 0x1FFu, s7 = (xrw[i + 7] >> j) & 0x1FFu;
        unsigned s8 = (xrw[i + 8] >> j) & 0x1FFu;
        win[w][p * 3 + 0] = s0 | (s1 << 9) | (s2 << 18);
        win[w][p * 3 + 1] = s3 | (s4 << 9) | (s5 << 18);
        win[w][p * 3 + 2] = s6 | (s7 << 9) | (s8 << 18);
    }
    __syncwarp();

    unsigned* outp = &g_a1[n * 400];
    const unsigned* wb = win[w];
    for (int i = 0; i < 20; i++) {
        unsigned myw = 0;
#pragma unroll
        for (int j = 0; j < 20; j++) {
            int p3 = (i * 20 + j) * 3;
            int acc = __popc(wb[p3] ^ fw0) + __popc(wb[p3 + 1] ^ fw1)
                    + __popc(wb[p3 + 2] ^ fw2);
            unsigned b = __ballot_sync(FULLMASK, acc <= mylim);
            if (lane == j) myw = b;
        }
        if (lane < 20) outp[i * 20 + lane] = myw;
    }
}

// ---------------- suma1: count a1 bits; last block -> g_lim2 ---------------
// 400 blocks: 400 px * 256 chunks of 32 images. Byte-sliced counting:
// cnt8[c] bytes accumulate channels {c, c+8, c+16, c+24}; counts <= 32.
__global__ __launch_bounds__(256) void suma1k() {
    int tg = blockIdx.x * 256 + threadIdx.x;       // 102400
    int p = tg % 400, chunk = tg / 400;
    unsigned cnt8[8];
#pragma unroll
    for (int c = 0; c < 8; c++) cnt8[c] = 0;
    const unsigned* base = &g_a1[(size_t)chunk * 32 * 400 + p];
#pragma unroll 16
    for (int k = 0; k < 32; k++) {
        unsigned wd = base[k * 400];
#pragma unroll
        for (int c = 0; c < 8; c++) cnt8[c] += (wd >> c) & 0x01010101u;
    }
#pragma unroll
    for (int c = 0; c < 8; c++)
#pragma unroll
        for (int b = 0; b < 4; b++)
            atomicAdd(&g_S1[p * 32 + c + 8 * b], (int)((cnt8[c] >> (8 * b)) & 0xFFu));

    __shared__ int R[20 * 9 * 32];
    __shared__ int WS[2592];
    __shared__ int lastf;
    __threadfence();
    if (threadIdx.x == 0) lastf = (atomicAdd(&g_c1, 1) == (int)gridDim.x - 1);
    __syncthreads();
    if (!lastf) return;
    __threadfence();
    int tid = threadIdx.x;
    for (int e = tid; e < 5760; e += 256) {
        int c = e & 31, rv = e >> 5, r = rv / 9, v = rv % 9, s = 0;
#pragma unroll
        for (int j = 0; j < 12; j++) s += g_S1[(r * 20 + j + v) * 32 + c];
        R[e] = s;
    }
    __syncthreads();
    for (int e = tid; e < 2592; e += 256) {
        int c = e & 31, uv = e >> 5, u = uv / 9, v = uv % 9, s = 0;
#pragma unroll
        for (int i = 0; i < 12; i++) s += R[((i + u) * 9 + v) * 32 + c];
        WS[e] = 2 * s - 1179648;
    }
    __syncthreads();
    int lane = tid & 31, wp = tid >> 5;
    for (int ff = 0; ff < 2; ff++) {
        int f = wp * 2 + ff;
        long long s = 0;
        for (int t = lane; t < 81; t += 32) {
            unsigned wdw = g_w2p[f * 81 + t];
#pragma unroll
            for (int c = 0; c < 32; c++) {
                int term = WS[t * 32 + c];
                s += ((wdw >> c) & 1u) ? term : -term;
            }
        }
        for (int o = 16; o > 0; o >>= 1) s += __shfl_down_sync(FULLMASK, s, o);
        if (lane == 0) {
            int t2 = (int)ceil((double)s / 1179648.0);
            g_lim2[f] = (2592 - t2) >> 1;
        }
    }
}

// ------------------------------ conv2 --------------------------------------
// 2 images/block, 384 threads, 1 task/thread: task = (img, f, row-pair, j-half).
// warp w: img = w/6, row-pair = w%6; half-warp = j-half, lane&15 = filter.
__global__ __launch_bounds__(384) void conv2k() {
    __shared__ unsigned xs[2][440];
    __shared__ unsigned ws[1296];
    __shared__ int lim[16];
    int tid = threadIdx.x, lane = tid & 31;
    int n0 = blockIdx.x * 2;
    for (int t = tid; t < 800; t += 384) {
        int im = t / 400;
        xs[im][t - im * 400] = g_a1[(size_t)n0 * 400 + t];
    }
    for (int t = tid; t < 1296; t += 384) ws[t] = g_w2p[t];
    if (tid < 16) lim[tid] = g_lim2[tid];
    __syncthreads();

    int f = tid & 15;
    int jh = (tid >> 4) & 1;
    int w = tid >> 5;
    int img = w / 6, ip = w - img * 6;     // row-pair 0..5
    int i0 = ip * 2;
    const unsigned* wb = &ws[f * 81];
    const unsigned* xbase = &xs[img][i0 * 20 + jh * 6];

    unsigned rb0[14], rb1[14], rb2[14];
    int at[6], ab[6];
#pragma unroll
    for (int k = 0; k < 6; k++) { at[k] = 0; ab[k] = 0; }
#pragma unroll
    for (int v = 0; v < 14; v++) { rb0[v] = xbase[v]; rb1[v] = xbase[20 + v]; }

#define C2BODY(TP, BT, NX, U)                                            \
    {                                                                    \
        _Pragma("unroll")                                                \
        for (int v = 0; v < 14; v++) NX[v] = xbase[((U) + 2) * 20 + v];  \
        _Pragma("unroll")                                                \
        for (int v = 0; v < 9; v++) {                                    \
            unsigned wv = wb[(U) * 9 + v];                               \
            _Pragma("unroll")                                            \
            for (int jj = 0; jj < 6; jj++) {                             \
                at[jj] += __popc(TP[jj + v] ^ wv);                       \
                ab[jj] += __popc(BT[jj + v] ^ wv);                       \
            }                                                            \
        }                                                                \
    }

#pragma unroll 1
    for (int uu = 0; uu < 9; uu += 3) {
        C2BODY(rb0, rb1, rb2, uu + 0);
        C2BODY(rb1, rb2, rb0, uu + 1);
        C2BODY(rb2, rb0, rb1, uu + 2);
    }
#undef C2BODY

    int limf = lim[f];
    unsigned myword = 0;
#pragma unroll
    for (int k = 0; k < 6; k++) {
        unsigned b = __ballot_sync(FULLMASK, at[k] <= limf);
        if ((lane & 15) == k) myword = (lane < 16) ? (b & 0xFFFFu) : (b >> 16);
    }
#pragma unroll
    for (int k = 0; k < 6; k++) {
        unsigned b = __ballot_sync(FULLMASK, ab[k] <= limf);
        if ((lane & 15) == k + 6) myword = (lane < 16) ? (b & 0xFFFFu) : (b >> 16);
    }
    int kl = lane & 15;
    if (kl < 12) {
        int row = i0 + (kl >= 6);
        int col = jh * 6 + (kl % 6);
        g_a2[(size_t)(n0 + img) * 144 + row * 12 + col] = (unsigned short)myword;
    }
}

// ---------------- suma2: count a2 bits; last block -> g_lim3 ---------------
// 144 blocks: 144 px * 256 chunks of 32 images. Byte-sliced counting.
__global__ __launch_bounds__(256) void suma2k() {
    int tg = blockIdx.x * 256 + threadIdx.x;       // 36864
    int p = tg % 144, chunk = tg / 144;
    unsigned cnt8[8];
#pragma unroll
    for (int c = 0; c < 8; c++) cnt8[c] = 0;
    const unsigned short* base = &g_a2[(size_t)chunk * 32 * 144 + p];
#pragma unroll 16
    for (int k = 0; k < 32; k++) {
        unsigned wd = base[k * 144];
#pragma unroll
        for (int c = 0; c < 8; c++) cnt8[c] += (wd >> c) & 0x01010101u;
    }
#pragma unroll
    for (int c = 0; c < 8; c++)
#pragma unroll
        for (int b = 0; b < 2; b++)
            atomicAdd(&g_S2[p * 16 + c + 8 * b], (int)((cnt8[c] >> (8 * b)) & 0xFFu));

    __shared__ int WS[1296];
    __shared__ int lastf;
    __threadfence();
    if (threadIdx.x == 0) lastf = (atomicAdd(&g_c2, 1) == (int)gridDim.x - 1);
    __syncthreads();
    if (!lastf) return;
    __threadfence();
    int tid = threadIdx.x;
    for (int e = tid; e < 1296; e += 256) {
        int c = e & 15, uv = e >> 4, u = uv / 9, v = uv % 9, s = 0;
#pragma unroll
        for (int i = 0; i < 4; i++)
#pragma unroll
            for (int j = 0; j < 4; j++)
                s += g_S2[((i + u) * 12 + (j + v)) * 16 + c];
        WS[e] = 2 * s - 131072;
    }
    __syncthreads();
    int lane = tid & 31, f = tid >> 5;
    long long s = 0;
    for (int t = lane; t < 81; t += 32) {
        unsigned wdw = g_w3p[f * 81 + t];
#pragma unroll
        for (int c = 0; c < 16; c++) {
            int term = WS[(t << 4) + c];
            s += ((wdw >> c) & 1u) ? term : -term;
        }
    }
    for (int o = 16; o > 0; o >>= 1) s += __shfl_down_sync(FULLMASK, s, o);
    if (lane == 0) {
        int t3 = (int)ceil((double)s / 131072.0);
        g_lim3[f] = (1296 - t3) >> 1;
    }
}

// --------------- conv3 + binarize + linear layer, fused --------------------
__global__ __launch_bounds__(256) void conv34k(float* __restrict__ out) {
    __shared__ unsigned short xs[2][144];
    __shared__ unsigned short ws[8 * 88];   // stride 88 kills bank conflicts
    __shared__ int lim[8];
    __shared__ unsigned a3s[2][4];
    int tid = threadIdx.x;
    int n0 = blockIdx.x * 2;
    for (int t = tid; t < 288; t += 256) {
        int img = t / 144, pp = t % 144;
        xs[img][pp] = g_a2[(size_t)(n0 + img) * 144 + pp];
    }
    for (int t = tid; t < 648; t += 256) {
        int f = t / 81, k = t % 81;
        ws[f * 88 + k] = g_w3p[t];
    }
    if (tid < 8) lim[tid] = g_lim3[tid];
    __syncthreads();
    int half = tid >> 7, ht = tid & 127;
    int f = ht & 7, pix = ht >> 3, i = pix >> 2, j = pix & 3;
    const unsigned short* xb = &xs[half][i * 12 + j];
    const unsigned short* wb = &ws[f * 88];
    int acc = 0;
#pragma unroll
    for (int u = 0; u < 9; u++)
#pragma unroll
        for (int v = 0; v < 9; v++)
            acc += __popc((unsigned)(xb[u * 12 + v] ^ wb[u * 9 + v]));
    // ballot word (pix>>2) with bit ((pix&3)*8+f) — exactly g_wlp layout
    unsigned bw = __ballot_sync(FULLMASK, acc <= lim[f]);
    if ((tid & 31) == 0) a3s[half][ht >> 5] = bw;
    __syncthreads();
    if (ht < 10) {
        const unsigned* wp = &g_wlp[ht * 4];
        int pop = 0;
#pragma unroll
        for (int p4 = 0; p4 < 4; p4++) pop += __popc(a3s[half][p4] ^ wp[p4]);
        out[(n0 + half) * 10 + ht] = (float)(128 - 2 * pop) + g_sbl[ht];
    }
}

// ------------------------------ launch -------------------------------------
// Inputs identified BY ELEMENT COUNT (all 9 distinct): robust to any order.
extern "C" void kernel_launch(void* const* d_in, const int* in_sizes, int n_in,
                              void* d_out, int out_size) {
    (void)out_size;
    const float *x = 0, *w1 = 0, *w2 = 0, *w3 = 0, *wl = 0, *bl = 0;
    for (int i = 0; i < n_in; i++) {
        const float* p = (const float*)d_in[i];
        switch (in_sizes[i]) {
            case 6422528: x  = p; break;
            case 2592:    w1 = p; break;
            case 41472:   w2 = p; break;
            case 10368:   w3 = p; break;
            case 1280:    wl = p; break;
            case 10:      bl = p; break;
            default: break;   // b1/b2/b3 cancel under BN+sign
        }
    }
    prepk   <<<50,   256>>>(w1, w2, w3, wl, bl);
    binxk   <<<1024, 256>>>(x);
    conv1k  <<<1024, 256>>>();
    suma1k  <<<400,  256>>>();
    conv2k  <<<4096, 384>>>();
    suma2k  <<<144,  256>>>();
    conv34k <<<4096, 256>>>((float*)d_out);
}